// round 16
// baseline (speedup 1.0000x reference)
#include <cuda_runtime.h>
#include <cuda_fp16.h>
#include <math.h>
#include <stdint.h>

#define N_NODES 50000
#define N_EDGES 800000
#define E_TOT   (N_EDGES + N_NODES)
#define FDIM    512
#define HEADS   8
#define HID     64
#define NEG_SLOPE 0.2f

#define KP0 96
#define WOFF0 0
#define WOFF1 (FDIM * KP0)
#define WOFF2 (WOFF1 + FDIM * FDIM)
#define WTOT  (WOFF2 + FDIM * FDIM)

// ---------------- scratch (device globals; no allocs allowed) ----------------
__device__ float  g_hA[(size_t)N_NODES * FDIM];
__device__ __half g_Ahi[(size_t)N_NODES * FDIM];
__device__ __half g_Alo[(size_t)N_NODES * FDIM];
__device__ __half g_Wthi[WTOT];
__device__ __half g_Wtlo[WTOT];
__device__ float  g_asrc[N_NODES * HEADS];
__device__ float  g_adst[N_NODES * HEADS];
__device__ int    g_deg[N_NODES];
__device__ int    g_rowptr[N_NODES + 1];
__device__ int    g_rowcur[N_NODES];
__device__ int    g_srclist[E_TOT];

// ============================ helpers ============================
__device__ __forceinline__ uint32_t smem_u32(const void* p) {
    uint32_t a;
    asm("{ .reg .u64 t; cvta.to.shared.u64 t, %1; cvt.u32.u64 %0, t; }" : "=r"(a) : "l"(p));
    return a;
}
__device__ __forceinline__ void mma_f16(float* d, const uint32_t* a, const uint32_t* b) {
    asm volatile(
        "mma.sync.aligned.m16n8k16.row.col.f32.f16.f16.f32 "
        "{%0,%1,%2,%3}, {%4,%5,%6,%7}, {%8,%9}, {%0,%1,%2,%3};"
        : "+f"(d[0]), "+f"(d[1]), "+f"(d[2]), "+f"(d[3])
        : "r"(a[0]), "r"(a[1]), "r"(a[2]), "r"(a[3]), "r"(b[0]), "r"(b[1]));
}
__device__ __forceinline__ void ldsm_x4(uint32_t& r0, uint32_t& r1, uint32_t& r2,
                                        uint32_t& r3, uint32_t addr) {
    asm volatile("ldmatrix.sync.aligned.m8n8.x4.shared.b16 {%0,%1,%2,%3}, [%4];"
                 : "=r"(r0), "=r"(r1), "=r"(r2), "=r"(r3) : "r"(addr));
}
__device__ __forceinline__ void cp_async16(uint32_t saddr, const void* gaddr, int src_bytes) {
    asm volatile("cp.async.cg.shared.global [%0], [%1], 16, %2;"
                 :: "r"(saddr), "l"(gaddr), "r"(src_bytes));
}
#define CP_COMMIT() asm volatile("cp.async.commit_group;" ::: "memory")
#define CP_WAIT(n)  asm volatile("cp.async.wait_group %0;" :: "n"(n) : "memory")

// ============================ CSR build ============================
__global__ void zero_deg_kernel() {
    int i = blockIdx.x * blockDim.x + threadIdx.x;
    if (i < N_NODES) g_deg[i] = 0;
}
__global__ void count_kernel(const int* __restrict__ ei) {
    int idx = blockIdx.x * blockDim.x + threadIdx.x;
    if (idx >= E_TOT) return;
    int dst = (idx < N_EDGES) ? ei[N_EDGES + idx] : (idx - N_EDGES);
    atomicAdd(&g_deg[dst], 1);
}
__global__ void scan_kernel() {
    __shared__ int sums[1024];
    const int per = (N_NODES + 1023) / 1024;
    int t  = threadIdx.x;
    int lo = t * per;
    int hi = min(lo + per, N_NODES);
    int s = 0;
    for (int i = lo; i < hi; i++) s += g_deg[i];
    sums[t] = s;
    __syncthreads();
    if (t == 0) {
        int run = 0;
        for (int i = 0; i < 1024; i++) { int v = sums[i]; sums[i] = run; run += v; }
        g_rowptr[N_NODES] = run;
    }
    __syncthreads();
    int run = sums[t];
    for (int i = lo; i < hi; i++) {
        g_rowptr[i] = run;
        g_rowcur[i] = run;
        run += g_deg[i];
    }
}
__global__ void fill_kernel(const int* __restrict__ ei) {
    int idx = blockIdx.x * blockDim.x + threadIdx.x;
    if (idx >= E_TOT) return;
    int src, dst;
    if (idx < N_EDGES) { src = ei[idx]; dst = ei[N_EDGES + idx]; }
    else               { src = dst = idx - N_EDGES; }
    int pos = atomicAdd(&g_rowcur[dst], 1);
    g_srclist[pos] = src;
}

// ============================ fp16 hi/lo conversions ============================
__global__ void convert_x_kernel(const float* __restrict__ x) {
    int idx = blockIdx.x * blockDim.x + threadIdx.x;
    if (idx >= N_NODES * KP0) return;
    int n = idx / KP0, k = idx % KP0;
    float v = (k < 69) ? x[n * 69 + k] : 0.f;
    __half h = __float2half_rn(v);
    g_Ahi[idx] = h;
    g_Alo[idx] = __float2half_rn(v - __half2float(h));
}
__global__ void convert_w_all_kernel(const float* __restrict__ W0,
                                     const float* __restrict__ W1,
                                     const float* __restrict__ W2) {
    int idx = blockIdx.x * blockDim.x + threadIdx.x;
    if (idx >= WTOT) return;
    const float* W;
    int K, Kp, off;
    if (idx < WOFF1)      { W = W0; K = 69;   Kp = KP0;  off = 0; }
    else if (idx < WOFF2) { W = W1; K = FDIM; Kp = FDIM; off = WOFF1; }
    else                  { W = W2; K = FDIM; Kp = FDIM; off = WOFF2; }
    int li = idx - off;
    int n = li / Kp, k = li % Kp;
    float v = (k < K) ? W[(size_t)k * FDIM + n] : 0.f;
    __half h = __float2half_rn(v);
    g_Wthi[idx] = h;
    g_Wtlo[idx] = __float2half_rn(v - __half2float(h));
}

// ============================ fp16 3-term warp-MMA GEMM + fused alpha ============
// BK=32, 64B rows, XOR swizzle g ^ ((row>>1)&3), 3-stage cp.async pipe, 2 CTAs/SM,
// A-pair MMA scheduling (accumulator reuse distance 8)
#define BM 128
#define BN 128
#define BK 32
#define ROWB 64
#define TILEB (128 * ROWB)
#define STAGEB (4 * TILEB)
#define NSTAGE 3
#define SMEM_GEMM (NSTAGE * STAGEB + 128 * 4 * 4)

__device__ __forceinline__ uint32_t swadr(uint32_t tilebase, int row, int g, int rx) {
    return tilebase + row * ROWB + (((g) ^ rx) << 4);
}

__global__ __launch_bounds__(256, 2) void mma_gemm_kernel(
    const __half* __restrict__ Ahi, const __half* __restrict__ Alo,
    const __half* __restrict__ Bhi, const __half* __restrict__ Blo,
    float* __restrict__ C, const float* __restrict__ aSrc, const float* __restrict__ aDst,
    int nrows, int Kp)
{
    extern __shared__ __half smh[];
    float* salpha = (float*)((char*)smh + NSTAGE * STAGEB);

    const int tid  = threadIdx.x;
    const int wid  = tid >> 5;
    const int lane = tid & 31;
    const int gid  = lane >> 2;
    const int tig  = lane & 3;
    const int warp_m = wid >> 2;
    const int warp_n = wid & 3;
    const int rowBase = blockIdx.y * BM;
    const int nBase   = blockIdx.x * BN;

    const int nch = Kp / BK;

    float acc[4][4][4];
#pragma unroll
    for (int i = 0; i < 4; i++)
#pragma unroll
        for (int j = 0; j < 4; j++)
#pragma unroll
            for (int q = 0; q < 4; q++) acc[i][j][q] = 0.f;

    const int lrow = tid >> 1, lseg = tid & 1;
    const int lrx  = (lrow >> 1) & 3;
    const int arow = rowBase + lrow;
    const int aok  = (arow < nrows) ? 16 : 0;
    const __half* gAhi = Ahi + (size_t)(aok ? arow : 0) * Kp + lseg * 16;
    const __half* gAlo = Alo + (size_t)(aok ? arow : 0) * Kp + lseg * 16;
    const __half* gBhi = Bhi + (size_t)(nBase + lrow) * Kp + lseg * 16;
    const __half* gBlo = Blo + (size_t)(nBase + lrow) * Kp + lseg * 16;
    const uint32_t sbase = smem_u32(smh);

    const int aX = ((lane & 15) >> 1) & 3;
    const int bX = (lane & 7) >> 1;
    const int aRow0 = warp_m * 64 + (lane & 15);
    const int aG0   = lane >> 4;
    const int bRow0 = warp_n * 32 + ((lane >> 4) << 3) + (lane & 7);
    const int bG0   = (lane >> 3) & 1;

    auto loadChunk = [&](int ic, int buf) {
        const int k0 = ic * BK;
        const uint32_t sb = sbase + buf * STAGEB;
#pragma unroll
        for (int j = 0; j < 2; j++) {
            int g = lseg * 2 + j;
            cp_async16(swadr(sb,             lrow, g, lrx), gAhi + k0 + j * 8, aok);
            cp_async16(swadr(sb + TILEB,     lrow, g, lrx), gAlo + k0 + j * 8, aok);
            cp_async16(swadr(sb + 2 * TILEB, lrow, g, lrx), gBhi + k0 + j * 8, 16);
            cp_async16(swadr(sb + 3 * TILEB, lrow, g, lrx), gBlo + k0 + j * 8, 16);
        }
        CP_COMMIT();
    };

    loadChunk(0, 0);
    if (nch > 1) loadChunk(1, 1);
    if (tid < 128) {
        salpha[tid * 4 + 0] = 0.f; salpha[tid * 4 + 1] = 0.f;
        salpha[tid * 4 + 2] = 0.f; salpha[tid * 4 + 3] = 0.f;
    }

    int buf = 0;
    for (int ic = 0; ic < nch; ic++) {
        if (ic + 2 < nch) { loadChunk(ic + 2, (ic + 2) % NSTAGE); CP_WAIT(2); }
        else if (ic + 1 < nch) { CP_WAIT(1); }
        else { CP_WAIT(0); }
        __syncthreads();

        const uint32_t asHb = sbase + buf * STAGEB;
        const uint32_t asLb = asHb + TILEB;
        const uint32_t bsHb = asHb + 2 * TILEB;
        const uint32_t bsLb = asHb + 3 * TILEB;

#pragma unroll
        for (int kk = 0; kk < BK; kk += 16) {
            const int gk = kk >> 3;
            uint32_t bhi[4][2], blo[4][2];
            ldsm_x4(bhi[0][0], bhi[0][1], bhi[1][0], bhi[1][1],
                    swadr(bsHb, bRow0,      bG0 + gk, bX));
            ldsm_x4(bhi[2][0], bhi[2][1], bhi[3][0], bhi[3][1],
                    swadr(bsHb, bRow0 + 16, bG0 + gk, bX));
            ldsm_x4(blo[0][0], blo[0][1], blo[1][0], blo[1][1],
                    swadr(bsLb, bRow0,      bG0 + gk, bX));
            ldsm_x4(blo[2][0], blo[2][1], blo[3][0], blo[3][1],
                    swadr(bsLb, bRow0 + 16, bG0 + gk, bX));
            // A-pair scheduling: acc reuse distance 8
#pragma unroll
            for (int mtp = 0; mtp < 4; mtp += 2) {
                uint32_t ahi0[4], alo0[4], ahi1[4], alo1[4];
                ldsm_x4(ahi0[0], ahi0[1], ahi0[2], ahi0[3],
                        swadr(asHb, aRow0 + mtp * 16,       aG0 + gk, aX));
                ldsm_x4(ahi1[0], ahi1[1], ahi1[2], ahi1[3],
                        swadr(asHb, aRow0 + (mtp + 1) * 16, aG0 + gk, aX));
                ldsm_x4(alo0[0], alo0[1], alo0[2], alo0[3],
                        swadr(asLb, aRow0 + mtp * 16,       aG0 + gk, aX));
                ldsm_x4(alo1[0], alo1[1], alo1[2], alo1[3],
                        swadr(asLb, aRow0 + (mtp + 1) * 16, aG0 + gk, aX));
#pragma unroll
                for (int nt = 0; nt < 4; nt++)
                    mma_f16(acc[mtp][nt], ahi0, bhi[nt]);
#pragma unroll
                for (int nt = 0; nt < 4; nt++)
                    mma_f16(acc[mtp + 1][nt], ahi1, bhi[nt]);
#pragma unroll
                for (int nt = 0; nt < 4; nt++)
                    mma_f16(acc[mtp][nt], ahi0, blo[nt]);
#pragma unroll
                for (int nt = 0; nt < 4; nt++)
                    mma_f16(acc[mtp + 1][nt], ahi1, blo[nt]);
#pragma unroll
                for (int nt = 0; nt < 4; nt++)
                    mma_f16(acc[mtp][nt], alo0, bhi[nt]);
#pragma unroll
                for (int nt = 0; nt < 4; nt++)
                    mma_f16(acc[mtp + 1][nt], alo1, bhi[nt]);
            }
        }
        __syncthreads();
        buf = (buf + 1 == NSTAGE) ? 0 : buf + 1;
    }

    // ---- epilogue: store C + fused alpha partial dots ----
    const int hl = warp_n >> 1;
    float s1[4][2], s2[4][2];
#pragma unroll
    for (int mt = 0; mt < 4; mt++) { s1[mt][0]=0.f; s1[mt][1]=0.f; s2[mt][0]=0.f; s2[mt][1]=0.f; }

#pragma unroll
    for (int mt = 0; mt < 4; mt++) {
        int r0 = rowBase + warp_m * 64 + mt * 16 + gid;
        int r1 = r0 + 8;
#pragma unroll
        for (int nt = 0; nt < 4; nt++) {
            int col = nBase + warp_n * 32 + nt * 8 + 2 * tig;
            float2 aS2 = *(const float2*)(aSrc + col);
            float2 aD2 = *(const float2*)(aDst + col);
            if (r0 < nrows)
                *(float2*)(C + (size_t)r0 * FDIM + col) =
                    make_float2(acc[mt][nt][0], acc[mt][nt][1]);
            if (r1 < nrows)
                *(float2*)(C + (size_t)r1 * FDIM + col) =
                    make_float2(acc[mt][nt][2], acc[mt][nt][3]);
            s1[mt][0] += acc[mt][nt][0] * aS2.x + acc[mt][nt][1] * aS2.y;
            s2[mt][0] += acc[mt][nt][0] * aD2.x + acc[mt][nt][1] * aD2.y;
            s1[mt][1] += acc[mt][nt][2] * aS2.x + acc[mt][nt][3] * aS2.y;
            s2[mt][1] += acc[mt][nt][2] * aD2.x + acc[mt][nt][3] * aD2.y;
        }
    }
#pragma unroll
    for (int mt = 0; mt < 4; mt++)
#pragma unroll
        for (int j = 0; j < 2; j++) {
            s1[mt][j] += __shfl_down_sync(0xffffffffu, s1[mt][j], 2, 4);
            s1[mt][j] += __shfl_down_sync(0xffffffffu, s1[mt][j], 1, 4);
            s2[mt][j] += __shfl_down_sync(0xffffffffu, s2[mt][j], 2, 4);
            s2[mt][j] += __shfl_down_sync(0xffffffffu, s2[mt][j], 1, 4);
        }
    if (tig == 0) {
#pragma unroll
        for (int mt = 0; mt < 4; mt++) {
            int lr0 = warp_m * 64 + mt * 16 + gid;
            atomicAdd(&salpha[lr0 * 4 + hl * 2 + 0], s1[mt][0]);
            atomicAdd(&salpha[lr0 * 4 + hl * 2 + 1], s2[mt][0]);
            atomicAdd(&salpha[(lr0 + 8) * 4 + hl * 2 + 0], s1[mt][1]);
            atomicAdd(&salpha[(lr0 + 8) * 4 + hl * 2 + 1], s2[mt][1]);
        }
    }
    __syncthreads();
    if (tid < 128) {
        int grow = rowBase + tid;
        if (grow < nrows) {
            int hbase = (nBase >> 6);
            g_asrc[grow * HEADS + hbase]     = salpha[tid * 4 + 0];
            g_adst[grow * HEADS + hbase]     = salpha[tid * 4 + 1];
            g_asrc[grow * HEADS + hbase + 1] = salpha[tid * 4 + 2];
            g_adst[grow * HEADS + hbase + 1] = salpha[tid * 4 + 3];
        }
    }
}

// ---------------- fused online-softmax aggregation ----------------
#define AGG_CHUNK 256
__global__ __launch_bounds__(128) void aggregate_kernel(
    const float* __restrict__ h, const float* __restrict__ bias,
    __half* __restrict__ outHi, __half* __restrict__ outLo,
    const float* __restrict__ predW, const float* __restrict__ predb,
    float* __restrict__ out, int mode)
{
    int d = blockIdx.x;
    int t = threadIdx.x;            // 128 threads, 4 channels each
    int head = t >> 4;
    int start = g_rowptr[d], end = g_rowptr[d + 1];
    float adst_v = g_adst[d * HEADS + head];

    __shared__ int ssrc[AGG_CHUNK];
    __shared__ float spred[3];

    float m = -INFINITY, denom = 0.f;
    float4 acc = make_float4(0.f, 0.f, 0.f, 0.f);

    for (int base = start; base < end; base += AGG_CHUNK) {
        int cnt = min(AGG_CHUNK, end - base);
        __syncthreads();
        for (int i = t; i < cnt; i += 128) ssrc[i] = g_srclist[base + i];
        if (t < 3 && base == start) spred[t] = 0.f;
        __syncthreads();
#pragma unroll 4
        for (int i = 0; i < cnt; i++) {
            int s = ssrc[i];
            float e = g_asrc[s * HEADS + head] + adst_v;
            e = (e > 0.f) ? e : NEG_SLOPE * e;
            if (e > m) {
                float sc = __expf(m - e);
                m = e;
                denom *= sc;
                acc.x *= sc; acc.y *= sc; acc.z *= sc; acc.w *= sc;
            }
            float w = __expf(e - m);
            denom += w;
            float4 hv = *(const float4*)(h + (size_t)s * FDIM + t * 4);
            acc.x += w * hv.x; acc.y += w * hv.y;
            acc.z += w * hv.z; acc.w += w * hv.w;
        }
    }

    float inv = 1.f / (denom + 1e-16f);
    float4 b4 = *(const float4*)(bias + t * 4);
    float4 o;
    o.x = acc.x * inv + b4.x; o.y = acc.y * inv + b4.y;
    o.z = acc.z * inv + b4.z; o.w = acc.w * inv + b4.w;

    if (mode == 0) {
        o.x = fmaxf(o.x, 0.f); o.y = fmaxf(o.y, 0.f);
        o.z = fmaxf(o.z, 0.f); o.w = fmaxf(o.w, 0.f);
        size_t idx = (size_t)d * FDIM + t * 4;
        __half hx = __float2half_rn(o.x), hy = __float2half_rn(o.y);
        __half hz = __float2half_rn(o.z), hw = __float2half_rn(o.w);
        __half2* ph = (__half2*)(outHi + idx);
        ph[0] = __halves2half2(hx, hy);
        ph[1] = __halves2half2(hz, hw);
        __half2* pl = (__half2*)(outLo + idx);
        pl[0] = __halves2half2(__float2half_rn(o.x - __half2float(hx)),
                               __float2half_rn(o.y - __half2float(hy)));
        pl[1] = __halves2half2(__float2half_rn(o.z - __half2float(hz)),
                               __float2half_rn(o.w - __half2float(hw)));
    } else {
        int c0 = t * 4;
        float p0 = o.x * predW[(c0+0)*3+0] + o.y * predW[(c0+1)*3+0]
                 + o.z * predW[(c0+2)*3+0] + o.w * predW[(c0+3)*3+0];
        float p1 = o.x * predW[(c0+0)*3+1] + o.y * predW[(c0+1)*3+1]
                 + o.z * predW[(c0+2)*3+1] + o.w * predW[(c0+3)*3+1];
        float p2 = o.x * predW[(c0+0)*3+2] + o.y * predW[(c0+1)*3+2]
                 + o.z * predW[(c0+2)*3+2] + o.w * predW[(c0+3)*3+2];
#pragma unroll
        for (int off = 16; off > 0; off >>= 1) {
            p0 += __shfl_down_sync(0xffffffffu, p0, off);
            p1 += __shfl_down_sync(0xffffffffu, p1, off);
            p2 += __shfl_down_sync(0xffffffffu, p2, off);
        }
        if ((t & 31) == 0) {
            atomicAdd(&spred[0], p0);
            atomicAdd(&spred[1], p1);
            atomicAdd(&spred[2], p2);
        }
        __syncthreads();
        if (t < 3) out[d * 3 + t] = spred[t] + predb[t];
    }
}

// ---------------- launch ----------------
extern "C" void kernel_launch(void* const* d_in, const int* in_sizes, int n_in,
                              void* d_out, int out_size)
{
    const float* x     = (const float*)d_in[0];   // [N,69]
    const int*   ei    = (const int*)  d_in[1];   // [2,E]
    const float* W[3]    = {(const float*)d_in[3],  (const float*)d_in[7],  (const float*)d_in[11]};
    const float* aS[3]   = {(const float*)d_in[4],  (const float*)d_in[8],  (const float*)d_in[12]};
    const float* aD[3]   = {(const float*)d_in[5],  (const float*)d_in[9],  (const float*)d_in[13]};
    const float* bb[3]   = {(const float*)d_in[6],  (const float*)d_in[10], (const float*)d_in[14]};
    const float* predW = (const float*)d_in[15];
    const float* predb = (const float*)d_in[16];
    float* out = (float*)d_out;

    float*  hA;  cudaGetSymbolAddress((void**)&hA,  g_hA);
    __half* Ahi; cudaGetSymbolAddress((void**)&Ahi, g_Ahi);
    __half* Alo; cudaGetSymbolAddress((void**)&Alo, g_Alo);
    __half* Whi; cudaGetSymbolAddress((void**)&Whi, g_Wthi);
    __half* Wlo; cudaGetSymbolAddress((void**)&Wlo, g_Wtlo);

    cudaFuncSetAttribute(mma_gemm_kernel,
                         cudaFuncAttributeMaxDynamicSharedMemorySize, SMEM_GEMM);

    const int  K_in[3] = {KP0, FDIM, FDIM};
    const int  woff[3] = {WOFF0, WOFF1, WOFF2};
    dim3 ggrid(FDIM / BN, (N_NODES + BM - 1) / BM);

    // launches 1-4: zero, convert_x, convert_w_all, GEMM layer 0 (GEMM = #4 for ncu)
    zero_deg_kernel<<<(N_NODES + 255) / 256, 256>>>();
    convert_x_kernel<<<(N_NODES * KP0 + 255) / 256, 256>>>(x);
    convert_w_all_kernel<<<(WTOT + 255) / 256, 256>>>(W[0], W[1], W[2]);
    mma_gemm_kernel<<<ggrid, 256, SMEM_GEMM>>>(Ahi, Alo, Whi + woff[0], Wlo + woff[0],
                                               hA, aS[0], aD[0], N_NODES, K_in[0]);
    // CSR build (needed only by aggregate)
    count_kernel<<<(E_TOT + 255) / 256, 256>>>(ei);
    scan_kernel<<<1, 1024>>>();
    fill_kernel<<<(E_TOT + 255) / 256, 256>>>(ei);

    aggregate_kernel<<<N_NODES, 128>>>(hA, bb[0], Ahi, Alo, predW, predb, out, 0);

    for (int l = 1; l < 3; l++) {
        mma_gemm_kernel<<<ggrid, 256, SMEM_GEMM>>>(Ahi, Alo, Whi + woff[l], Wlo + woff[l],
                                                   hA, aS[l], aD[l], N_NODES, K_in[l]);
        aggregate_kernel<<<N_NODES, 128>>>(hA, bb[l], Ahi, Alo,
                                           predW, predb, out, (l == 2) ? 1 : 0);
    }
}

// round 17
// speedup vs baseline: 1.0156x; 1.0156x over previous
#include <cuda_runtime.h>
#include <cuda_fp16.h>
#include <math.h>
#include <stdint.h>

#define N_NODES 50000
#define N_EDGES 800000
#define E_TOT   (N_EDGES + N_NODES)
#define FDIM    512
#define HEADS   8
#define HID     64
#define NEG_SLOPE 0.2f

#define KP0 96
#define WOFF0 0
#define WOFF1 (FDIM * KP0)
#define WOFF2 (WOFF1 + FDIM * FDIM)
#define WTOT  (WOFF2 + FDIM * FDIM)

// ---------------- scratch (device globals; no allocs allowed) ----------------
__device__ float  g_hA[(size_t)N_NODES * FDIM];
__device__ __half g_Ahi[(size_t)N_NODES * FDIM];
__device__ __half g_Alo[(size_t)N_NODES * FDIM];
__device__ __half g_Wthi[WTOT];
__device__ __half g_Wtlo[WTOT];
__device__ float  g_asrc[N_NODES * HEADS];
__device__ float  g_adst[N_NODES * HEADS];
__device__ int    g_deg[N_NODES];
__device__ int    g_rowptr[N_NODES + 1];
__device__ int    g_rowcur[N_NODES];
__device__ int    g_srclist[E_TOT];

// ============================ helpers ============================
__device__ __forceinline__ uint32_t smem_u32(const void* p) {
    uint32_t a;
    asm("{ .reg .u64 t; cvta.to.shared.u64 t, %1; cvt.u32.u64 %0, t; }" : "=r"(a) : "l"(p));
    return a;
}
__device__ __forceinline__ void mma_f16(float* d, const uint32_t* a, const uint32_t* b) {
    asm volatile(
        "mma.sync.aligned.m16n8k16.row.col.f32.f16.f16.f32 "
        "{%0,%1,%2,%3}, {%4,%5,%6,%7}, {%8,%9}, {%0,%1,%2,%3};"
        : "+f"(d[0]), "+f"(d[1]), "+f"(d[2]), "+f"(d[3])
        : "r"(a[0]), "r"(a[1]), "r"(a[2]), "r"(a[3]), "r"(b[0]), "r"(b[1]));
}
__device__ __forceinline__ void ldsm_x4(uint32_t& r0, uint32_t& r1, uint32_t& r2,
                                        uint32_t& r3, uint32_t addr) {
    asm volatile("ldmatrix.sync.aligned.m8n8.x4.shared.b16 {%0,%1,%2,%3}, [%4];"
                 : "=r"(r0), "=r"(r1), "=r"(r2), "=r"(r3) : "r"(addr));
}
__device__ __forceinline__ void cp_async16(uint32_t saddr, const void* gaddr, int src_bytes) {
    asm volatile("cp.async.cg.shared.global [%0], [%1], 16, %2;"
                 :: "r"(saddr), "l"(gaddr), "r"(src_bytes));
}
#define CP_COMMIT() asm volatile("cp.async.commit_group;" ::: "memory")
#define CP_WAIT(n)  asm volatile("cp.async.wait_group %0;" :: "n"(n) : "memory")

// ============================ CSR build ============================
__global__ void zero_deg_kernel() {
    int i = blockIdx.x * blockDim.x + threadIdx.x;
    if (i < N_NODES) g_deg[i] = 0;
}
__global__ void count_kernel(const int* __restrict__ ei) {
    int idx = blockIdx.x * blockDim.x + threadIdx.x;
    if (idx >= E_TOT) return;
    int dst = (idx < N_EDGES) ? ei[N_EDGES + idx] : (idx - N_EDGES);
    atomicAdd(&g_deg[dst], 1);
}
__global__ void scan_kernel() {
    __shared__ int sums[1024];
    const int per = (N_NODES + 1023) / 1024;
    int t  = threadIdx.x;
    int lo = t * per;
    int hi = min(lo + per, N_NODES);
    int s = 0;
    for (int i = lo; i < hi; i++) s += g_deg[i];
    sums[t] = s;
    __syncthreads();
    if (t == 0) {
        int run = 0;
        for (int i = 0; i < 1024; i++) { int v = sums[i]; sums[i] = run; run += v; }
        g_rowptr[N_NODES] = run;
    }
    __syncthreads();
    int run = sums[t];
    for (int i = lo; i < hi; i++) {
        g_rowptr[i] = run;
        g_rowcur[i] = run;
        run += g_deg[i];
    }
}
__global__ void fill_kernel(const int* __restrict__ ei) {
    int idx = blockIdx.x * blockDim.x + threadIdx.x;
    if (idx >= E_TOT) return;
    int src, dst;
    if (idx < N_EDGES) { src = ei[idx]; dst = ei[N_EDGES + idx]; }
    else               { src = dst = idx - N_EDGES; }
    int pos = atomicAdd(&g_rowcur[dst], 1);
    g_srclist[pos] = src;
}

// ============================ fp16 hi/lo conversions ============================
__global__ void convert_x_kernel(const float* __restrict__ x) {
    int idx = blockIdx.x * blockDim.x + threadIdx.x;
    if (idx >= N_NODES * KP0) return;
    int n = idx / KP0, k = idx % KP0;
    float v = (k < 69) ? x[n * 69 + k] : 0.f;
    __half h = __float2half_rn(v);
    g_Ahi[idx] = h;
    g_Alo[idx] = __float2half_rn(v - __half2float(h));
}
__global__ void convert_w_all_kernel(const float* __restrict__ W0,
                                     const float* __restrict__ W1,
                                     const float* __restrict__ W2) {
    int idx = blockIdx.x * blockDim.x + threadIdx.x;
    if (idx >= WTOT) return;
    const float* W;
    int K, Kp, off;
    if (idx < WOFF1)      { W = W0; K = 69;   Kp = KP0;  off = 0; }
    else if (idx < WOFF2) { W = W1; K = FDIM; Kp = FDIM; off = WOFF1; }
    else                  { W = W2; K = FDIM; Kp = FDIM; off = WOFF2; }
    int li = idx - off;
    int n = li / Kp, k = li % Kp;
    float v = (k < K) ? W[(size_t)k * FDIM + n] : 0.f;
    __half h = __float2half_rn(v);
    g_Wthi[idx] = h;
    g_Wtlo[idx] = __float2half_rn(v - __half2float(h));
}

// ============================ fp16 3-term warp-MMA GEMM + fused alpha ============
// BK=32, 64B rows, XOR swizzle g ^ ((row>>1)&3), 3-stage cp.async pipe, 2 CTAs/SM
#define BM 128
#define BN 128
#define BK 32
#define ROWB 64
#define TILEB (128 * ROWB)
#define STAGEB (4 * TILEB)
#define NSTAGE 3
#define SMEM_GEMM (NSTAGE * STAGEB + 128 * 4 * 4)

__device__ __forceinline__ uint32_t swadr(uint32_t tilebase, int row, int g, int rx) {
    return tilebase + row * ROWB + (((g) ^ rx) << 4);
}

__global__ __launch_bounds__(256, 2) void mma_gemm_kernel(
    const __half* __restrict__ Ahi, const __half* __restrict__ Alo,
    const __half* __restrict__ Bhi, const __half* __restrict__ Blo,
    float* __restrict__ C, const float* __restrict__ aSrc, const float* __restrict__ aDst,
    int nrows, int Kp)
{
    extern __shared__ __half smh[];
    float* salpha = (float*)((char*)smh + NSTAGE * STAGEB);

    const int tid  = threadIdx.x;
    const int wid  = tid >> 5;
    const int lane = tid & 31;
    const int gid  = lane >> 2;
    const int tig  = lane & 3;
    const int warp_m = wid >> 2;
    const int warp_n = wid & 3;
    const int rowBase = blockIdx.y * BM;
    const int nBase   = blockIdx.x * BN;

    const int nch = Kp / BK;

    float acc[4][4][4];
#pragma unroll
    for (int i = 0; i < 4; i++)
#pragma unroll
        for (int j = 0; j < 4; j++)
#pragma unroll
            for (int q = 0; q < 4; q++) acc[i][j][q] = 0.f;

    const int lrow = tid >> 1, lseg = tid & 1;
    const int lrx  = (lrow >> 1) & 3;
    const int arow = rowBase + lrow;
    const int aok  = (arow < nrows) ? 16 : 0;
    const __half* gAhi = Ahi + (size_t)(aok ? arow : 0) * Kp + lseg * 16;
    const __half* gAlo = Alo + (size_t)(aok ? arow : 0) * Kp + lseg * 16;
    const __half* gBhi = Bhi + (size_t)(nBase + lrow) * Kp + lseg * 16;
    const __half* gBlo = Blo + (size_t)(nBase + lrow) * Kp + lseg * 16;
    const uint32_t sbase = smem_u32(smh);

    const int aX = ((lane & 15) >> 1) & 3;
    const int bX = (lane & 7) >> 1;
    const int aRow0 = warp_m * 64 + (lane & 15);
    const int aG0   = lane >> 4;
    const int bRow0 = warp_n * 32 + ((lane >> 4) << 3) + (lane & 7);
    const int bG0   = (lane >> 3) & 1;

    auto loadChunk = [&](int ic, int buf) {
        const int k0 = ic * BK;
        const uint32_t sb = sbase + buf * STAGEB;
#pragma unroll
        for (int j = 0; j < 2; j++) {
            int g = lseg * 2 + j;
            cp_async16(swadr(sb,             lrow, g, lrx), gAhi + k0 + j * 8, aok);
            cp_async16(swadr(sb + TILEB,     lrow, g, lrx), gAlo + k0 + j * 8, aok);
            cp_async16(swadr(sb + 2 * TILEB, lrow, g, lrx), gBhi + k0 + j * 8, 16);
            cp_async16(swadr(sb + 3 * TILEB, lrow, g, lrx), gBlo + k0 + j * 8, 16);
        }
        CP_COMMIT();
    };

    loadChunk(0, 0);
    if (nch > 1) loadChunk(1, 1);
    if (tid < 128) {
        salpha[tid * 4 + 0] = 0.f; salpha[tid * 4 + 1] = 0.f;
        salpha[tid * 4 + 2] = 0.f; salpha[tid * 4 + 3] = 0.f;
    }

    int buf = 0;
    for (int ic = 0; ic < nch; ic++) {
        if (ic + 2 < nch) { loadChunk(ic + 2, (ic + 2) % NSTAGE); CP_WAIT(2); }
        else if (ic + 1 < nch) { CP_WAIT(1); }
        else { CP_WAIT(0); }
        __syncthreads();

        const uint32_t asHb = sbase + buf * STAGEB;
        const uint32_t asLb = asHb + TILEB;
        const uint32_t bsHb = asHb + 2 * TILEB;
        const uint32_t bsLb = asHb + 3 * TILEB;

#pragma unroll
        for (int kk = 0; kk < BK; kk += 16) {
            const int gk = kk >> 3;
            uint32_t bhi[4][2], blo[4][2];
            ldsm_x4(bhi[0][0], bhi[0][1], bhi[1][0], bhi[1][1],
                    swadr(bsHb, bRow0,      bG0 + gk, bX));
            ldsm_x4(bhi[2][0], bhi[2][1], bhi[3][0], bhi[3][1],
                    swadr(bsHb, bRow0 + 16, bG0 + gk, bX));
            ldsm_x4(blo[0][0], blo[0][1], blo[1][0], blo[1][1],
                    swadr(bsLb, bRow0,      bG0 + gk, bX));
            ldsm_x4(blo[2][0], blo[2][1], blo[3][0], blo[3][1],
                    swadr(bsLb, bRow0 + 16, bG0 + gk, bX));
#pragma unroll
            for (int mt = 0; mt < 4; mt++) {
                uint32_t ahi[4], alo[4];
                ldsm_x4(ahi[0], ahi[1], ahi[2], ahi[3],
                        swadr(asHb, aRow0 + mt * 16, aG0 + gk, aX));
                ldsm_x4(alo[0], alo[1], alo[2], alo[3],
                        swadr(asLb, aRow0 + mt * 16, aG0 + gk, aX));
#pragma unroll
                for (int nt = 0; nt < 4; nt++)
                    mma_f16(acc[mt][nt], ahi, bhi[nt]);
#pragma unroll
                for (int nt = 0; nt < 4; nt++)
                    mma_f16(acc[mt][nt], ahi, blo[nt]);
#pragma unroll
                for (int nt = 0; nt < 4; nt++)
                    mma_f16(acc[mt][nt], alo, bhi[nt]);
            }
        }
        __syncthreads();
        buf = (buf + 1 == NSTAGE) ? 0 : buf + 1;
    }

    // ---- epilogue: store C + fused alpha partial dots ----
    const int hl = warp_n >> 1;
    float s1[4][2], s2[4][2];
#pragma unroll
    for (int mt = 0; mt < 4; mt++) { s1[mt][0]=0.f; s1[mt][1]=0.f; s2[mt][0]=0.f; s2[mt][1]=0.f; }

#pragma unroll
    for (int mt = 0; mt < 4; mt++) {
        int r0 = rowBase + warp_m * 64 + mt * 16 + gid;
        int r1 = r0 + 8;
#pragma unroll
        for (int nt = 0; nt < 4; nt++) {
            int col = nBase + warp_n * 32 + nt * 8 + 2 * tig;
            float2 aS2 = *(const float2*)(aSrc + col);
            float2 aD2 = *(const float2*)(aDst + col);
            if (r0 < nrows)
                *(float2*)(C + (size_t)r0 * FDIM + col) =
                    make_float2(acc[mt][nt][0], acc[mt][nt][1]);
            if (r1 < nrows)
                *(float2*)(C + (size_t)r1 * FDIM + col) =
                    make_float2(acc[mt][nt][2], acc[mt][nt][3]);
            s1[mt][0] += acc[mt][nt][0] * aS2.x + acc[mt][nt][1] * aS2.y;
            s2[mt][0] += acc[mt][nt][0] * aD2.x + acc[mt][nt][1] * aD2.y;
            s1[mt][1] += acc[mt][nt][2] * aS2.x + acc[mt][nt][3] * aS2.y;
            s2[mt][1] += acc[mt][nt][2] * aD2.x + acc[mt][nt][3] * aD2.y;
        }
    }
#pragma unroll
    for (int mt = 0; mt < 4; mt++)
#pragma unroll
        for (int j = 0; j < 2; j++) {
            s1[mt][j] += __shfl_down_sync(0xffffffffu, s1[mt][j], 2, 4);
            s1[mt][j] += __shfl_down_sync(0xffffffffu, s1[mt][j], 1, 4);
            s2[mt][j] += __shfl_down_sync(0xffffffffu, s2[mt][j], 2, 4);
            s2[mt][j] += __shfl_down_sync(0xffffffffu, s2[mt][j], 1, 4);
        }
    if (tig == 0) {
#pragma unroll
        for (int mt = 0; mt < 4; mt++) {
            int lr0 = warp_m * 64 + mt * 16 + gid;
            atomicAdd(&salpha[lr0 * 4 + hl * 2 + 0], s1[mt][0]);
            atomicAdd(&salpha[lr0 * 4 + hl * 2 + 1], s2[mt][0]);
            atomicAdd(&salpha[(lr0 + 8) * 4 + hl * 2 + 0], s1[mt][1]);
            atomicAdd(&salpha[(lr0 + 8) * 4 + hl * 2 + 1], s2[mt][1]);
        }
    }
    __syncthreads();
    if (tid < 128) {
        int grow = rowBase + tid;
        if (grow < nrows) {
            int hbase = (nBase >> 6);
            g_asrc[grow * HEADS + hbase]     = salpha[tid * 4 + 0];
            g_adst[grow * HEADS + hbase]     = salpha[tid * 4 + 1];
            g_asrc[grow * HEADS + hbase + 1] = salpha[tid * 4 + 2];
            g_adst[grow * HEADS + hbase + 1] = salpha[tid * 4 + 3];
        }
    }
}

// ---------------- fused online-softmax aggregation ----------------
#define AGG_CHUNK 256
__global__ __launch_bounds__(128) void aggregate_kernel(
    const float* __restrict__ h, const float* __restrict__ bias,
    __half* __restrict__ outHi, __half* __restrict__ outLo,
    const float* __restrict__ predW, const float* __restrict__ predb,
    float* __restrict__ out, int mode)
{
    int d = blockIdx.x;
    int t = threadIdx.x;            // 128 threads, 4 channels each
    int head = t >> 4;
    int start = g_rowptr[d], end = g_rowptr[d + 1];
    float adst_v = g_adst[d * HEADS + head];

    __shared__ int ssrc[AGG_CHUNK];
    __shared__ float spred[3];

    float m = -INFINITY, denom = 0.f;
    float4 acc = make_float4(0.f, 0.f, 0.f, 0.f);

    for (int base = start; base < end; base += AGG_CHUNK) {
        int cnt = min(AGG_CHUNK, end - base);
        __syncthreads();
        for (int i = t; i < cnt; i += 128) ssrc[i] = g_srclist[base + i];
        if (t < 3 && base == start) spred[t] = 0.f;
        __syncthreads();
#pragma unroll 4
        for (int i = 0; i < cnt; i++) {
            int s = ssrc[i];
            float e = g_asrc[s * HEADS + head] + adst_v;
            e = (e > 0.f) ? e : NEG_SLOPE * e;
            if (e > m) {
                float sc = __expf(m - e);
                m = e;
                denom *= sc;
                acc.x *= sc; acc.y *= sc; acc.z *= sc; acc.w *= sc;
            }
            float w = __expf(e - m);
            denom += w;
            float4 hv = *(const float4*)(h + (size_t)s * FDIM + t * 4);
            acc.x += w * hv.x; acc.y += w * hv.y;
            acc.z += w * hv.z; acc.w += w * hv.w;
        }
    }

    float inv = 1.f / (denom + 1e-16f);
    float4 b4 = *(const float4*)(bias + t * 4);
    float4 o;
    o.x = acc.x * inv + b4.x; o.y = acc.y * inv + b4.y;
    o.z = acc.z * inv + b4.z; o.w = acc.w * inv + b4.w;

    if (mode == 0) {
        o.x = fmaxf(o.x, 0.f); o.y = fmaxf(o.y, 0.f);
        o.z = fmaxf(o.z, 0.f); o.w = fmaxf(o.w, 0.f);
        size_t idx = (size_t)d * FDIM + t * 4;
        __half hx = __float2half_rn(o.x), hy = __float2half_rn(o.y);
        __half hz = __float2half_rn(o.z), hw = __float2half_rn(o.w);
        __half2* ph = (__half2*)(outHi + idx);
        ph[0] = __halves2half2(hx, hy);
        ph[1] = __halves2half2(hz, hw);
        __half2* pl = (__half2*)(outLo + idx);
        pl[0] = __halves2half2(__float2half_rn(o.x - __half2float(hx)),
                               __float2half_rn(o.y - __half2float(hy)));
        pl[1] = __halves2half2(__float2half_rn(o.z - __half2float(hz)),
                               __float2half_rn(o.w - __half2float(hw)));
    } else {
        int c0 = t * 4;
        float p0 = o.x * predW[(c0+0)*3+0] + o.y * predW[(c0+1)*3+0]
                 + o.z * predW[(c0+2)*3+0] + o.w * predW[(c0+3)*3+0];
        float p1 = o.x * predW[(c0+0)*3+1] + o.y * predW[(c0+1)*3+1]
                 + o.z * predW[(c0+2)*3+1] + o.w * predW[(c0+3)*3+1];
        float p2 = o.x * predW[(c0+0)*3+2] + o.y * predW[(c0+1)*3+2]
                 + o.z * predW[(c0+2)*3+2] + o.w * predW[(c0+3)*3+2];
#pragma unroll
        for (int off = 16; off > 0; off >>= 1) {
            p0 += __shfl_down_sync(0xffffffffu, p0, off);
            p1 += __shfl_down_sync(0xffffffffu, p1, off);
            p2 += __shfl_down_sync(0xffffffffu, p2, off);
        }
        if ((t & 31) == 0) {
            atomicAdd(&spred[0], p0);
            atomicAdd(&spred[1], p1);
            atomicAdd(&spred[2], p2);
        }
        __syncthreads();
        if (t < 3) out[d * 3 + t] = spred[t] + predb[t];
    }
}

// ---------------- launch ----------------
extern "C" void kernel_launch(void* const* d_in, const int* in_sizes, int n_in,
                              void* d_out, int out_size)
{
    const float* x     = (const float*)d_in[0];   // [N,69]
    const int*   ei    = (const int*)  d_in[1];   // [2,E]
    const float* W[3]    = {(const float*)d_in[3],  (const float*)d_in[7],  (const float*)d_in[11]};
    const float* aS[3]   = {(const float*)d_in[4],  (const float*)d_in[8],  (const float*)d_in[12]};
    const float* aD[3]   = {(const float*)d_in[5],  (const float*)d_in[9],  (const float*)d_in[13]};
    const float* bb[3]   = {(const float*)d_in[6],  (const float*)d_in[10], (const float*)d_in[14]};
    const float* predW = (const float*)d_in[15];
    const float* predb = (const float*)d_in[16];
    float* out = (float*)d_out;

    float*  hA;  cudaGetSymbolAddress((void**)&hA,  g_hA);
    __half* Ahi; cudaGetSymbolAddress((void**)&Ahi, g_Ahi);
    __half* Alo; cudaGetSymbolAddress((void**)&Alo, g_Alo);
    __half* Whi; cudaGetSymbolAddress((void**)&Whi, g_Wthi);
    __half* Wlo; cudaGetSymbolAddress((void**)&Wlo, g_Wtlo);

    cudaFuncSetAttribute(mma_gemm_kernel,
                         cudaFuncAttributeMaxDynamicSharedMemorySize, SMEM_GEMM);

    const int  K_in[3] = {KP0, FDIM, FDIM};
    const int  woff[3] = {WOFF0, WOFF1, WOFF2};
    dim3 ggrid(FDIM / BN, (N_NODES + BM - 1) / BM);

    // launches 1-4: zero, convert_x, convert_w_all, GEMM layer 0 (GEMM = #4 for ncu)
    zero_deg_kernel<<<(N_NODES + 255) / 256, 256>>>();
    convert_x_kernel<<<(N_NODES * KP0 + 255) / 256, 256>>>(x);
    convert_w_all_kernel<<<(WTOT + 255) / 256, 256>>>(W[0], W[1], W[2]);
    mma_gemm_kernel<<<ggrid, 256, SMEM_GEMM>>>(Ahi, Alo, Whi + woff[0], Wlo + woff[0],
                                               hA, aS[0], aD[0], N_NODES, K_in[0]);
    // CSR build (needed only by aggregate)
    count_kernel<<<(E_TOT + 255) / 256, 256>>>(ei);
    scan_kernel<<<1, 1024>>>();
    fill_kernel<<<(E_TOT + 255) / 256, 256>>>(ei);

    aggregate_kernel<<<N_NODES, 128>>>(hA, bb[0], Ahi, Alo, predW, predb, out, 0);

    for (int l = 1; l < 3; l++) {
        mma_gemm_kernel<<<ggrid, 256, SMEM_GEMM>>>(Ahi, Alo, Whi + woff[l], Wlo + woff[l],
                                                   hA, aS[l], aD[l], N_NODES, K_in[l]);
        aggregate_kernel<<<N_NODES, 128>>>(hA, bb[l], Ahi, Alo,
                                           predW, predb, out, (l == 2) ? 1 : 0);
    }
}